// round 15
// baseline (speedup 1.0000x reference)
#include <cuda_runtime.h>
#include <math.h>

#define BS 32
#define NA 8400
#define NC 80
#define NB 64
#define TOPKK 13
#define CAP 512
#define GC 32                    // 32x32 grid of 20px cells over [0,640)
#define INV_CELL 0.05f
#define FILLX 32                 // extra blockIdx.x lanes in k_rows for score zero-fill

#define OFF_LABELS 0
#define OFF_BBOX   (BS*NA)
#define OFF_SCORES (BS*NA + BS*NA*4)
#define OFF_FG     (OFF_SCORES + BS*NA*NC)
#define OFF_TGI    (OFF_FG + BS*NA)

// ---------------- scratch ----------------
__device__ unsigned long long g_maskbits[BS*NA];  // bit g = mask_pos(g,a) pre-dedup
__device__ unsigned long long g_pack    [BS*NA];  // max over pairs: (ov_bits<<8)|(63-g)
__device__ unsigned long long g_packsel [BS*NA];  // same pack, topk-selected pairs only
__device__ float              g_posalign[BS*NB];
__device__ float              g_posover [BS*NB];
__device__ int                g_tgi [BS*NA];
__device__ unsigned char      g_fgb [BS*NA];
__device__ float              g_amax[BS*NA];
__device__ int                g_lab [BS*NA];
// anchor spatial grid (anc is batch-independent)
__device__ int    g_cellstart[GC*GC + 1];
__device__ float2 g_ga [NA];     // anchor positions, cell-sorted
__device__ int    g_gai[NA];     // anchor indices,   cell-sorted

__device__ __forceinline__ bool ap_inb(float4 G, float2 ap)
{
    return ap.x > G.x && ap.y > G.y && ap.x < G.z && ap.y < G.w;
}

__device__ __forceinline__ int cell_of(float v)
{
    return min(max((int)(v * INV_CELL), 0), GC - 1);
}

// ---------------- K_prep: block 0 builds the anchor grid; others clear scratch ----------------
__global__ __launch_bounds__(1024) void k_prep(const float2* __restrict__ anc)
{
    if (blockIdx.x == 0) {
        __shared__ int s_cnt[GC*GC];
        __shared__ int s_off[GC*GC];
        int t = threadIdx.x;                 // 1024 == GC*GC
        s_cnt[t] = 0;
        __syncthreads();
        for (int a = t; a < NA; a += 1024) {
            float2 ap = anc[a];
            atomicAdd(&s_cnt[cell_of(ap.y)*GC + cell_of(ap.x)], 1);
        }
        __syncthreads();
        int orig = s_cnt[t];
        // inclusive Hillis-Steele scan in place
        for (int d = 1; d < 1024; d <<= 1) {
            int u = (t >= d) ? s_cnt[t - d] : 0;
            __syncthreads();
            s_cnt[t] += u;
            __syncthreads();
        }
        int excl = s_cnt[t] - orig;
        g_cellstart[t] = excl;
        if (t == 1023) g_cellstart[1024] = s_cnt[1023];
        s_off[t] = excl;
        __syncthreads();
        for (int a = t; a < NA; a += 1024) {
            float2 ap = anc[a];
            int c = cell_of(ap.y)*GC + cell_of(ap.x);
            int pos = atomicAdd(&s_off[c], 1);
            g_ga[pos]  = ap;
            g_gai[pos] = a;
        }
    } else {
        long i = (long)(blockIdx.x - 1) * 1024 + threadIdx.x;
        const int NPA = BS*NA*8/16;          // 134400 int4 per u64 array
        int4 z = make_int4(0,0,0,0);
        if      (i <   NPA) ((int4*)g_maskbits)[i        ] = z;
        else if (i < 2*NPA) ((int4*)g_packsel )[i -   NPA] = z;
        else if (i < 3*NPA) ((int4*)g_pack    )[i - 2*NPA] = z;
        if (i < BS*NB) { g_posalign[i] = 0.f; g_posover[i] = 0.f; }
    }
}

// ---------------- K_rows: per-(b,g) grid-gather metric + top-13; extra blocks zero scores ----------------
__global__ __launch_bounds__(128) void k_rows(
    const float*  __restrict__ pd_scores,
    const float4* __restrict__ pd_bboxes,
    const float2* __restrict__ anc,
    const int*    __restrict__ gt_labels,
    const float4* __restrict__ gt_bboxes,
    const float*  __restrict__ mask_gt,
    float* __restrict__ out)
{
    // ---- fill lanes: zero the 86 MB target_scores region on other SMs,
    // overlapping the store drain with the compute blocks' latency-bound work
    if (blockIdx.x >= NB) {
        int f = (blockIdx.x - NB) + FILLX * blockIdx.y;   // 0..1023
        const int CHUNK = BS*NA*NC/4 / (FILLX*BS);        // 5250 float4 per block
        float4* dst = (float4*)(out + OFF_SCORES) + (long)f * CHUNK;
        float4 z = make_float4(0.f,0.f,0.f,0.f);
        for (int i = threadIdx.x; i < CHUNK; i += 128)
            dst[i] = z;
        return;
    }

    int g = blockIdx.x, b = blockIdx.y;
    int row = b*NB + g;
    if (mask_gt[row] <= 0.f) return;   // masked rows contribute nothing

    __shared__ unsigned long long s_key[CAP];
    __shared__ float s_cov[CAP];
    __shared__ int   s_ca[CAP];
    __shared__ int   s_cnt;
    if (threadIdx.x == 0) s_cnt = 0;
    __syncthreads();

    float4 G = gt_bboxes[row];
    int lbl = gt_labels[row];
    float w1 = G.z - G.x, h1 = G.w - G.y + 1e-7f;
    float at1 = atanf(w1 / h1);
    float a1  = w1 * h1;

    const float4* pb = pd_bboxes + b*NA;
    const float*  sc = pd_scores + (long)b*NA*NC + lbl;

    int cx0 = cell_of(G.x), cx1 = cell_of(G.z);
    int cy0 = cell_of(G.y), cy1 = cell_of(G.w);

    for (int cy = cy0; cy <= cy1; ++cy) {
        int st = g_cellstart[cy*GC + cx0];
        int en = g_cellstart[cy*GC + cx1 + 1];   // contiguous cell-row slice
        for (int i = st + threadIdx.x; i < en; i += 128) {
            float2 ap = g_ga[i];
            if (!ap_inb(G, ap)) continue;        // strict in-box (== deltas.min > 1e-9)
            int a = g_gai[i];

            float4 p = pb[a];
            float iw = fminf(G.z, p.z) - fmaxf(G.x, p.x);
            float ih = fminf(G.w, p.w) - fmaxf(G.y, p.y);
            float inter = fmaxf(iw, 0.f) * fmaxf(ih, 0.f);
            float w2 = p.z - p.x, h2 = p.w - p.y + 1e-7f;
            float uni = a1 + w2*h2 - inter + 1e-7f;
            float iou = inter / uni;
            float cw = fmaxf(G.z, p.z) - fminf(G.x, p.x);
            float ch = fmaxf(G.w, p.w) - fminf(G.y, p.y);
            float c2 = cw*cw + ch*ch + 1e-7f;
            float dx = p.x + p.z - G.x - G.z;
            float dy = p.y + p.w - G.y - G.w;
            float rho2 = (dx*dx + dy*dy) * 0.25f;
            float dd = atanf(w2 / h2) - at1;
            float v = 0.4052847345693511f * dd * dd;   // 4/pi^2
            float alpha = v / (v - iou + (1.0f + 1e-7f));
            float ci = iou - (rho2 / c2 + v * alpha);
            float ov = fmaxf(ci, 0.f);
            if (ov <= 0.f) continue;

            // per-anchor argmax over g (ties -> lowest g, like jnp.argmax)
            unsigned long long pk =
                ((unsigned long long)__float_as_uint(ov) << 8) | (unsigned)(63 - g);
            atomicMax(&g_pack[b*NA + a], pk);

            float s  = sc[a * NC];
            float o2 = ov * ov;
            float al = s * o2 * o2 * o2;   // score^1 * ov^6
            if (al > 0.f) {
                int slot = atomicAdd(&s_cnt, 1);
                if (slot < CAP) {
                    s_key[slot] = ((unsigned long long)__float_as_uint(al) << 32)
                                | (unsigned)(NA - 1 - a);
                    s_cov[slot] = ov;
                    s_ca[slot]  = a;
                }
            }
        }
    }
    __syncthreads();

    // warp 0: top-13 (ties -> lowest anchor index; keys are a total order)
    if (threadIdx.x < 32) {
        int lane = threadIdx.x;
        int C = min(s_cnt, CAP);
        int npos = min(C, TOPKK);
        for (int it = 0; it < npos; ++it) {
            unsigned long long bk = 0; int bj = -1;
            for (int j = lane; j < C; j += 32) {
                unsigned long long k = s_key[j];
                if (k > bk) { bk = k; bj = j; }
            }
            #pragma unroll
            for (int off = 16; off; off >>= 1) {
                unsigned long long kk = __shfl_down_sync(0xffffffffu, bk, off);
                int jj = __shfl_down_sync(0xffffffffu, bj, off);
                if (kk > bk) { bk = kk; bj = jj; }
            }
            bj = __shfl_sync(0xffffffffu, bj, 0);
            if (lane == 0) {
                int a = s_ca[bj];
                atomicOr(&g_maskbits[b*NA + a], 1ull << g);  // positives are in-box
                unsigned long long pk =
                    ((unsigned long long)__float_as_uint(s_cov[bj]) << 8) | (unsigned)(63 - g);
                atomicMax(&g_packsel[b*NA + a], pk);
                s_key[bj] = 0;
            }
            __syncwarp();
        }
        // fewer than 13 positives: ref fills with lowest-index zero entries
        if (lane == 0 && C < TOPKK) {
            int rem = TOPKK - C;
            for (int a = 0; rem > 0 && a < NA; ++a) {
                bool member = false;
                for (int j = 0; j < C; ++j) if (s_ca[j] == a) { member = true; break; }
                if (member) continue;
                rem--;                              // slot consumed by this zero entry
                if (ap_inb(G, anc[a]))              // mask only if in-box (ov=0 -> no packsel)
                    atomicOr(&g_maskbits[b*NA + a], 1ull << g);
            }
        }
    }
}

// ---------------- K_assign: dedup + targets + pos-max ----------------
__global__ __launch_bounds__(256) void k_assign(
    const float*  __restrict__ pd_scores,
    const int*    __restrict__ gt_labels,
    const float4* __restrict__ gt_bboxes,
    float* __restrict__ out)
{
    int b = blockIdx.y;
    __shared__ int s_lbl[NB];
    if (threadIdx.x < NB) s_lbl[threadIdx.x] = gt_labels[b*NB + threadIdx.x];
    __syncthreads();

    int a = blockIdx.x * 256 + threadIdx.x;
    if (a >= NA) return;
    int ba = b*NA + a;

    unsigned long long m = g_maskbits[ba];
    int fg = __popcll(m);
    int tgi = 0; float ovv = 0.f;
    if (fg > 1) {               // multi-assigned -> argmax over masked overlaps (all g)
        unsigned long long pk = g_pack[ba];
        if (pk) {
            tgi = 63 - (int)(pk & 63ull);
            ovv = __uint_as_float((unsigned)(pk >> 8));
        }
    } else if (fg == 1) {
        tgi = __ffsll((long long)m) - 1;
        unsigned long long ps = g_packsel[ba];
        ovv = __uint_as_float((unsigned)(ps >> 8));
    }
    bool active = fg > 0;

    float am = 0.f;
    if (active && ovv > 0.f) {
        float s = pd_scores[(long)ba * NC + s_lbl[tgi]];
        float o2 = ovv * ovv;
        am = s * o2 * o2 * o2;   // identical recompute of align metric
    }
    if (active) {   // non-negative floats: int-compare atomicMax is exact
        atomicMax((int*)&g_posalign[b*NB + tgi], __float_as_int(am));
        atomicMax((int*)&g_posover [b*NB + tgi], __float_as_int(ovv));
    }

    int lab = max(s_lbl[tgi], 0);
    g_tgi[ba] = tgi; g_fgb[ba] = active; g_amax[ba] = am; g_lab[ba] = lab;

    out[OFF_LABELS + ba] = (float)lab;
    ((float4*)(out + OFF_BBOX))[ba] = gt_bboxes[b*NB + tgi];
    out[OFF_FG  + ba] = active ? 1.f : 0.f;
    out[OFF_TGI + ba] = (float)tgi;
}

// ---------------- K_scores: sparse one-hot scatter (region pre-zeroed in k_rows fill lanes) ----------------
__global__ __launch_bounds__(256) void k_scores(float* __restrict__ out)
{
    int ba = blockIdx.x * 256 + threadIdx.x;
    if (ba >= BS*NA) return;
    if (!g_fgb[ba]) return;
    int b = ba / NA;
    int tgi = g_tgi[ba];
    float pa = g_posalign[b*NB + tgi];
    float po = g_posover [b*NB + tgi];
    out[OFF_SCORES + (long)ba * NC + g_lab[ba]] = (g_amax[ba] * po) / (pa + 1e-9f);
}

// ---------------- launch ----------------
extern "C" void kernel_launch(void* const* d_in, const int* in_sizes, int n_in,
                              void* d_out, int out_size)
{
    const float*  pd_scores = (const float*) d_in[0];
    const float4* pd_bboxes = (const float4*)d_in[1];
    const float2* anc       = (const float2*)d_in[2];
    const int*    gt_labels = (const int*)   d_in[3];
    const float4* gt_bboxes = (const float4*)d_in[4];
    const float*  mask_gt   = (const float*) d_in[5];
    float* out = (float*)d_out;

    const int NPA = BS*NA*8/16;
    k_prep<<<1 + (3*NPA + 1023)/1024, 1024>>>(anc);

    dim3 grows(NB + FILLX, BS);   // 64 compute lanes + 32 fill lanes per batch
    k_rows<<<grows, 128>>>(pd_scores, pd_bboxes, anc, gt_labels, gt_bboxes, mask_gt, out);

    dim3 gassign((NA + 255)/256, BS);
    k_assign<<<gassign, 256>>>(pd_scores, gt_labels, gt_bboxes, out);

    k_scores<<<(BS*NA + 255)/256, 256>>>(out);
}

// round 16
// speedup vs baseline: 1.0232x; 1.0232x over previous
#include <cuda_runtime.h>
#include <math.h>

#define BS 32
#define NA 8400
#define NC 80
#define NB 64
#define TOPKK 13
#define CAP 512
#define GC 32                    // 32x32 grid of 20px cells over [0,640)
#define INV_CELL 0.05f
#define GRID 1024                // persistent mega-kernel blocks (co-resident)
#define NTH 128
#define RPB 263                  // ceil(BS*NA / GRID) score-rows per block

#define OFF_LABELS 0
#define OFF_BBOX   (BS*NA)
#define OFF_SCORES (BS*NA + BS*NA*4)
#define OFF_FG     (OFF_SCORES + BS*NA*NC)
#define OFF_TGI    (OFF_FG + BS*NA)

// ---------------- scratch ----------------
__device__ unsigned long long g_maskbits[BS*NA];  // bit g = mask_pos(g,a) pre-dedup
__device__ unsigned long long g_pack    [BS*NA];  // max over pairs: (ov_bits<<8)|(63-g)
__device__ unsigned long long g_packsel [BS*NA];  // same pack, topk-selected pairs only
__device__ float              g_posalign[BS*NB];
__device__ float              g_posover [BS*NB];
__device__ int                g_tgi [BS*NA];
__device__ unsigned char      g_fgb [BS*NA];
__device__ float              g_amax[BS*NA];
__device__ int                g_lab [BS*NA];
// anchor spatial grid (anc is batch-independent)
__device__ int    g_cellstart[GC*GC + 1];
__device__ float2 g_ga [NA];     // anchor positions, cell-sorted
__device__ int    g_gai[NA];     // anchor indices,   cell-sorted
// software grid barrier (self-resetting; gen monotonic across replays)
__device__ int               g_bar_cnt = 0;
__device__ volatile unsigned g_bar_gen = 0;

__device__ __forceinline__ bool ap_inb(float4 G, float2 ap)
{
    return ap.x > G.x && ap.y > G.y && ap.x < G.z && ap.y < G.w;
}

__device__ __forceinline__ int cell_of(float v)
{
    return min(max((int)(v * INV_CELL), 0), GC - 1);
}

__device__ __forceinline__ void gridbar()
{
    __syncthreads();
    __threadfence();
    if (threadIdx.x == 0) {
        unsigned gen = g_bar_gen;
        if (atomicAdd(&g_bar_cnt, 1) == GRID - 1) {
            g_bar_cnt = 0;
            __threadfence();
            g_bar_gen = gen + 1;
        } else {
            while (g_bar_gen == gen) __nanosleep(64);
        }
    }
    __syncthreads();
    __threadfence();
}

// ---------------- K_prep: block 0 builds the anchor grid; others clear scratch ----------------
__global__ __launch_bounds__(1024) void k_prep(const float2* __restrict__ anc)
{
    if (blockIdx.x == 0) {
        __shared__ int s_cnt[GC*GC];
        __shared__ int s_off[GC*GC];
        int t = threadIdx.x;                 // 1024 == GC*GC
        s_cnt[t] = 0;
        __syncthreads();
        for (int a = t; a < NA; a += 1024) {
            float2 ap = anc[a];
            atomicAdd(&s_cnt[cell_of(ap.y)*GC + cell_of(ap.x)], 1);
        }
        __syncthreads();
        int orig = s_cnt[t];
        // inclusive Hillis-Steele scan in place
        for (int d = 1; d < 1024; d <<= 1) {
            int u = (t >= d) ? s_cnt[t - d] : 0;
            __syncthreads();
            s_cnt[t] += u;
            __syncthreads();
        }
        int excl = s_cnt[t] - orig;
        g_cellstart[t] = excl;
        if (t == 1023) g_cellstart[1024] = s_cnt[1023];
        s_off[t] = excl;
        __syncthreads();
        for (int a = t; a < NA; a += 1024) {
            float2 ap = anc[a];
            int c = cell_of(ap.y)*GC + cell_of(ap.x);
            int pos = atomicAdd(&s_off[c], 1);
            g_ga[pos]  = ap;
            g_gai[pos] = a;
        }
    } else {
        long i = (long)(blockIdx.x - 1) * 1024 + threadIdx.x;
        const int NPA = BS*NA*8/16;          // 134400 int4 per u64 array
        int4 z = make_int4(0,0,0,0);
        if      (i <   NPA) ((int4*)g_maskbits)[i        ] = z;
        else if (i < 2*NPA) ((int4*)g_packsel )[i -   NPA] = z;
        else if (i < 3*NPA) ((int4*)g_pack    )[i - 2*NPA] = z;
        if (i < BS*NB) { g_posalign[i] = 0.f; g_posover[i] = 0.f; }
    }
}

// ---------------- K_mega: rows -> assign -> scores in one persistent launch ----------------
__global__ __launch_bounds__(NTH, 8) void k_mega(
    const float*  __restrict__ pd_scores,
    const float4* __restrict__ pd_bboxes,
    const float2* __restrict__ anc,
    const int*    __restrict__ gt_labels,
    const float4* __restrict__ gt_bboxes,
    const float*  __restrict__ mask_gt,
    float* __restrict__ out)
{
    __shared__ unsigned long long s_key[CAP];
    __shared__ float s_cov[CAP];
    __shared__ int   s_ca[CAP];
    __shared__ int   s_cnt;

    // ================= Phase 1: per-(b,g) grid-gather metric + top-13 =================
    for (int row = blockIdx.x; row < BS*NB; row += GRID) {   // 2 tasks per block
        int b = row / NB, g = row % NB;
        __syncthreads();                       // protect s_cnt reuse across tasks
        if (threadIdx.x == 0) s_cnt = 0;
        __syncthreads();

        bool valid = mask_gt[row] > 0.f;
        float4 G = gt_bboxes[row];
        if (valid) {
            int lbl = gt_labels[row];
            float w1 = G.z - G.x, h1 = G.w - G.y + 1e-7f;
            float at1 = atanf(w1 / h1);
            float a1  = w1 * h1;
            const float4* pb = pd_bboxes + b*NA;
            const float*  sc = pd_scores + (long)b*NA*NC + lbl;

            int cx0 = cell_of(G.x), cx1 = cell_of(G.z);
            int cy0 = cell_of(G.y), cy1 = cell_of(G.w);

            for (int cy = cy0; cy <= cy1; ++cy) {
                int st = g_cellstart[cy*GC + cx0];
                int en = g_cellstart[cy*GC + cx1 + 1];   // contiguous cell-row slice
                for (int i = st + threadIdx.x; i < en; i += NTH) {
                    float2 ap = g_ga[i];
                    if (!ap_inb(G, ap)) continue;        // strict in-box
                    int a = g_gai[i];

                    float4 p = pb[a];
                    float iw = fminf(G.z, p.z) - fmaxf(G.x, p.x);
                    float ih = fminf(G.w, p.w) - fmaxf(G.y, p.y);
                    float inter = fmaxf(iw, 0.f) * fmaxf(ih, 0.f);
                    float w2 = p.z - p.x, h2 = p.w - p.y + 1e-7f;
                    float uni = a1 + w2*h2 - inter + 1e-7f;
                    float iou = inter / uni;
                    float cw = fmaxf(G.z, p.z) - fminf(G.x, p.x);
                    float ch = fmaxf(G.w, p.w) - fminf(G.y, p.y);
                    float c2 = cw*cw + ch*ch + 1e-7f;
                    float dx = p.x + p.z - G.x - G.z;
                    float dy = p.y + p.w - G.y - G.w;
                    float rho2 = (dx*dx + dy*dy) * 0.25f;
                    float dd = atanf(w2 / h2) - at1;
                    float v = 0.4052847345693511f * dd * dd;   // 4/pi^2
                    float alpha = v / (v - iou + (1.0f + 1e-7f));
                    float ci = iou - (rho2 / c2 + v * alpha);
                    float ov = fmaxf(ci, 0.f);
                    if (ov <= 0.f) continue;

                    // per-anchor argmax over g (ties -> lowest g, like jnp.argmax)
                    unsigned long long pk =
                        ((unsigned long long)__float_as_uint(ov) << 8) | (unsigned)(63 - g);
                    atomicMax(&g_pack[b*NA + a], pk);

                    float s  = sc[a * NC];
                    float o2 = ov * ov;
                    float al = s * o2 * o2 * o2;   // score^1 * ov^6
                    if (al > 0.f) {
                        int slot = atomicAdd(&s_cnt, 1);
                        if (slot < CAP) {
                            s_key[slot] = ((unsigned long long)__float_as_uint(al) << 32)
                                        | (unsigned)(NA - 1 - a);
                            s_cov[slot] = ov;
                            s_ca[slot]  = a;
                        }
                    }
                }
            }
        }
        __syncthreads();

        // warp 0: top-13 (ties -> lowest anchor index; keys are a total order)
        if (valid && threadIdx.x < 32) {
            int lane = threadIdx.x;
            int C = min(s_cnt, CAP);
            int npos = min(C, TOPKK);
            for (int it = 0; it < npos; ++it) {
                unsigned long long bk = 0; int bj = -1;
                for (int j = lane; j < C; j += 32) {
                    unsigned long long k = s_key[j];
                    if (k > bk) { bk = k; bj = j; }
                }
                #pragma unroll
                for (int off = 16; off; off >>= 1) {
                    unsigned long long kk = __shfl_down_sync(0xffffffffu, bk, off);
                    int jj = __shfl_down_sync(0xffffffffu, bj, off);
                    if (kk > bk) { bk = kk; bj = jj; }
                }
                bj = __shfl_sync(0xffffffffu, bj, 0);
                if (lane == 0) {
                    int a = s_ca[bj];
                    atomicOr(&g_maskbits[b*NA + a], 1ull << g);  // positives are in-box
                    unsigned long long pk =
                        ((unsigned long long)__float_as_uint(s_cov[bj]) << 8) | (unsigned)(63 - g);
                    atomicMax(&g_packsel[b*NA + a], pk);
                    s_key[bj] = 0;
                }
                __syncwarp();
            }
            // fewer than 13 positives: ref fills with lowest-index zero entries
            if (lane == 0 && C < TOPKK) {
                int rem = TOPKK - C;
                for (int a = 0; rem > 0 && a < NA; ++a) {
                    bool member = false;
                    for (int j = 0; j < C; ++j) if (s_ca[j] == a) { member = true; break; }
                    if (member) continue;
                    rem--;                              // slot consumed by this zero entry
                    if (ap_inb(G, anc[a]))              // mask only if in-box
                        atomicOr(&g_maskbits[b*NA + a], 1ull << g);
                }
            }
        }
    }

    gridbar();   // all maskbits/packsel/pack complete

    // ================= Phase 2: per-anchor dedup + targets + pos-max =================
    for (int ba = blockIdx.x * NTH + threadIdx.x; ba < BS*NA; ba += GRID*NTH) {
        int b = ba / NA;

        unsigned long long m = g_maskbits[ba];
        int fg = __popcll(m);
        int tgi = 0; float ovv = 0.f;
        if (fg > 1) {               // multi-assigned -> argmax over masked overlaps
            unsigned long long pk = g_pack[ba];
            if (pk) {
                tgi = 63 - (int)(pk & 63ull);
                ovv = __uint_as_float((unsigned)(pk >> 8));
            }
        } else if (fg == 1) {
            tgi = __ffsll((long long)m) - 1;
            unsigned long long ps = g_packsel[ba];
            ovv = __uint_as_float((unsigned)(ps >> 8));
        }
        bool active = fg > 0;

        int lblg = gt_labels[b*NB + tgi];      // L2-hot (8 KB table)
        float am = 0.f;
        if (active && ovv > 0.f) {
            float s = pd_scores[(long)ba * NC + lblg];
            float o2 = ovv * ovv;
            am = s * o2 * o2 * o2;   // identical recompute of align metric
        }
        if (active) {   // non-negative floats: int-compare atomicMax is exact
            atomicMax((int*)&g_posalign[b*NB + tgi], __float_as_int(am));
            atomicMax((int*)&g_posover [b*NB + tgi], __float_as_int(ovv));
        }

        int lab = max(lblg, 0);
        g_tgi[ba] = tgi; g_fgb[ba] = active; g_amax[ba] = am; g_lab[ba] = lab;

        out[OFF_LABELS + ba] = (float)lab;
        ((float4*)(out + OFF_BBOX))[ba] = gt_bboxes[b*NB + tgi];
        out[OFF_FG  + ba] = active ? 1.f : 0.f;
        out[OFF_TGI + ba] = (float)tgi;
    }

    gridbar();   // pos-max arrays complete

    // ================= Phase 3: scores fill + scatter (own disjoint row slice) =======
    {
        int r0 = blockIdx.x * RPB;
        int rcnt = min(RPB, BS*NA - r0);
        if (rcnt > 0) {
            float4* dst = (float4*)(out + OFF_SCORES) + (long)r0 * (NC/4);
            float4 z = make_float4(0.f,0.f,0.f,0.f);
            for (int i = threadIdx.x; i < rcnt * (NC/4); i += NTH)
                dst[i] = z;
            __syncthreads();   // block's zeros before its own scatter
            for (int i = threadIdx.x; i < rcnt; i += NTH) {
                int ba = r0 + i;
                if (g_fgb[ba]) {
                    int b = ba / NA;
                    int tgi = g_tgi[ba];
                    float pa = g_posalign[b*NB + tgi];
                    float po = g_posover [b*NB + tgi];
                    out[OFF_SCORES + (long)ba * NC + g_lab[ba]] =
                        (g_amax[ba] * po) / (pa + 1e-9f);
                }
            }
        }
    }
}

// ---------------- launch ----------------
extern "C" void kernel_launch(void* const* d_in, const int* in_sizes, int n_in,
                              void* d_out, int out_size)
{
    const float*  pd_scores = (const float*) d_in[0];
    const float4* pd_bboxes = (const float4*)d_in[1];
    const float2* anc       = (const float2*)d_in[2];
    const int*    gt_labels = (const int*)   d_in[3];
    const float4* gt_bboxes = (const float4*)d_in[4];
    const float*  mask_gt   = (const float*) d_in[5];
    float* out = (float*)d_out;

    const int NPA = BS*NA*8/16;
    k_prep<<<1 + (3*NPA + 1023)/1024, 1024>>>(anc);

    k_mega<<<GRID, NTH>>>(pd_scores, pd_bboxes, anc, gt_labels, gt_bboxes, mask_gt, out);
}